// round 1
// baseline (speedup 1.0000x reference)
#include <cuda_runtime.h>
#include <float.h>

// Problem constants (from reference)
#define NS   32
#define NH   32
#define KVH  8
#define QPK  4
#define HS   128
#define BS   16
#define MB   128
#define PART 256
#define NPARTS 8                 // MB*BS / PART = 2048/256
#define SCALE 0.08838834764831843f   // 1/sqrt(128)

// Split-K partial scratch (4MB + 32KB)
__device__ float g_pout[(size_t)NS*KVH*QPK*NPARTS*HS];
__device__ float g_pm[NS*KVH*QPK*NPARTS];
__device__ float g_pl[NS*KVH*QPK*NPARTS];

// One CTA = (kv_head h, partition p, seq n). 256 threads.
// Phase 1: warp-per-token logits (QPK=4 query heads share each K load).
// Phase 2: thread-per-dim V accumulation with float4 over the contiguous s axis.
__global__ __launch_bounds__(256) void attn_partial(
    const float* __restrict__ q,    const float* __restrict__ knew,
    const float* __restrict__ vnew, const float* __restrict__ kc,
    const float* __restrict__ vc,   const int*   __restrict__ bt,
    const int*   __restrict__ ctx)
{
    int h = blockIdx.x, p = blockIdx.y, n = blockIdx.z;
    int L = ctx[n];
    int start = p * PART;
    if (start >= L) return;               // uniform across CTA
    int ntok = min(PART, L - start);

    __shared__ float s_logits[QPK][PART]; // raw logits, then exp values
    __shared__ float s_m[QPK][8];
    __shared__ float s_mf[QPK];
    __shared__ float s_lred[QPK][8];

    int tid  = threadIdx.x;
    int lane = tid & 31, w = tid >> 5;

    // Per-lane query fragment: hd = 4*lane .. 4*lane+3 for each of 4 heads
    float4 qv[QPK];
#pragma unroll
    for (int qi = 0; qi < QPK; qi++)
        qv[qi] = ((const float4*)(q + ((size_t)n*NH + h*QPK + qi)*HS))[lane];

    float mloc[QPK];
#pragma unroll
    for (int qi = 0; qi < QPK; qi++) mloc[qi] = -FLT_MAX;

    // ---- Phase 1: logits ----
    for (int t = start + w; t < start + ntok; t += 8) {
        float4 kv;
        if (t == L - 1) {
            // new token's K comes from the `key` input (cache not yet written)
            kv = ((const float4*)(knew + ((size_t)n*KVH + h)*HS))[lane];
        } else {
            int blk = bt[n*MB + (t >> 4)];
            int s   = t & 15;
            // key_cache[b,h,d,s,x]: (blk*KVH+h)*2048 + d*128 + s*8 + x
            // lane's hd = 4*lane -> d = lane>>1, x = (lane&1)*4  (16B aligned)
            const float* base = kc + ((size_t)blk*KVH + h)*(HS*BS);
            kv = *(const float4*)(base + (lane >> 1)*128 + s*8 + (lane & 1)*4);
        }
        float dot[QPK];
#pragma unroll
        for (int qi = 0; qi < QPK; qi++)
            dot[qi] = kv.x*qv[qi].x + kv.y*qv[qi].y + kv.z*qv[qi].z + kv.w*qv[qi].w;
#pragma unroll
        for (int off = 16; off; off >>= 1)
#pragma unroll
            for (int qi = 0; qi < QPK; qi++)
                dot[qi] += __shfl_xor_sync(0xffffffffu, dot[qi], off);
#pragma unroll
        for (int qi = 0; qi < QPK; qi++) {
            float lg = dot[qi]*SCALE;
            mloc[qi] = fmaxf(mloc[qi], lg);
            if (lane == 0) s_logits[qi][t - start] = lg;
        }
    }
    if (lane == 0)
#pragma unroll
        for (int qi = 0; qi < QPK; qi++) s_m[qi][w] = mloc[qi];
    __syncthreads();

    if (tid < QPK) {
        float m = s_m[tid][0];
#pragma unroll
        for (int i = 1; i < 8; i++) m = fmaxf(m, s_m[tid][i]);
        s_mf[tid] = m;
    }
    __syncthreads();

    // ---- softmax numerator (unnormalized): exp(logit - m_part) ----
    float lsum[QPK];
#pragma unroll
    for (int qi = 0; qi < QPK; qi++) {
        float e = 0.f;
        if (tid < ntok) e = __expf(s_logits[qi][tid] - s_mf[qi]);
        s_logits[qi][tid] = e;    // positions >= ntok become 0
        lsum[qi] = e;
    }
#pragma unroll
    for (int off = 16; off; off >>= 1)
#pragma unroll
        for (int qi = 0; qi < QPK; qi++)
            lsum[qi] += __shfl_xor_sync(0xffffffffu, lsum[qi], off);
    if (lane == 0)
#pragma unroll
        for (int qi = 0; qi < QPK; qi++) s_lred[qi][w] = lsum[qi];
    __syncthreads();   // also publishes exp values for phase 2

    if (tid < QPK) {
        float l = 0.f;
#pragma unroll
        for (int i = 0; i < 8; i++) l += s_lred[tid][i];
        int pid = ((n*KVH + h)*QPK + tid)*NPARTS + p;
        g_pm[pid] = s_mf[tid];
        g_pl[pid] = l;
    }

    // ---- Phase 2: V accumulation ----
    int d  = tid & (HS - 1);
    int qh = tid >> 7;             // thread owns (qh, d) and (qh+2, d)
    float acc0 = 0.f, acc1 = 0.f;
    int nblk = (ntok + 15) >> 4;
    for (int b = 0; b < nblk; b++) {
        int blk = bt[n*MB + (start >> 4) + b];
        // value_cache[b,h,d,s]: fixed d -> 16 contiguous floats over s
        const float* vb = vc + (((size_t)blk*KVH + h)*HS + d)*BS;
        const float* p0 = &s_logits[qh][b*16];
        const float* p1 = &s_logits[qh + 2][b*16];
#pragma unroll
        for (int ss = 0; ss < 16; ss += 4) {
            float4 v4 = *(const float4*)(vb + ss);
            acc0 += p0[ss]*v4.x + p0[ss+1]*v4.y + p0[ss+2]*v4.z + p0[ss+3]*v4.w;
            acc1 += p1[ss]*v4.x + p1[ss+1]*v4.y + p1[ss+2]*v4.z + p1[ss+3]*v4.w;
        }
    }
    // Correct the new token: replace stale cached V with v_new contribution
    int tl = L - 1;
    if (tl >= start && tl < start + ntok) {
        int blk = bt[n*MB + (tl >> 4)];
        int s   = tl & 15;
        float vst  = vc[(((size_t)blk*KVH + h)*HS + d)*BS + s];
        float vnw  = vnew[((size_t)n*KVH + h)*HS + d];
        float diff = vnw - vst;
        acc0 += s_logits[qh][tl - start] * diff;
        acc1 += s_logits[qh + 2][tl - start] * diff;
    }
    size_t pid0 = (size_t)((n*KVH + h)*QPK + qh    )*NPARTS + p;
    size_t pid1 = (size_t)((n*KVH + h)*QPK + qh + 2)*NPARTS + p;
    g_pout[pid0*HS + d] = acc0;
    g_pout[pid1*HS + d] = acc1;
}

// One CTA per (n, h, qi): combine up to NPARTS partials, normalize, write out.
__global__ __launch_bounds__(128) void attn_reduce(
    const int* __restrict__ ctx, float* __restrict__ out)
{
    int g = blockIdx.x;                 // (n*KVH + h)*QPK + qi
    int n = g / (KVH*QPK);
    int head = g % (KVH*QPK);           // h*QPK + qi
    int L = ctx[n];
    int np = (L + PART - 1) / PART;
    int d = threadIdx.x;

    float m = -FLT_MAX;
    for (int p = 0; p < np; p++) m = fmaxf(m, g_pm[g*NPARTS + p]);
    float l = 0.f, o = 0.f;
    for (int p = 0; p < np; p++) {
        float a = __expf(g_pm[g*NPARTS + p] - m);
        l += a * g_pl[g*NPARTS + p];
        o += a * g_pout[((size_t)g*NPARTS + p)*HS + d];
    }
    out[((size_t)n*NH + head)*HS + d] = o / l;
}

extern "C" void kernel_launch(void* const* d_in, const int* in_sizes, int n_in,
                              void* d_out, int out_size)
{
    const float* q   = (const float*)d_in[0];
    const float* k   = (const float*)d_in[1];
    const float* v   = (const float*)d_in[2];
    const float* kc  = (const float*)d_in[3];
    const float* vc  = (const float*)d_in[4];
    const int*   bt  = (const int*)d_in[5];
    const int*   ctx = (const int*)d_in[6];
    // d_in[7] = slot_mapping (derivable from block_tables/context_lens; unused)

    dim3 g1(KVH, NPARTS, NS);
    attn_partial<<<g1, 256>>>(q, k, v, kc, vc, bt, ctx);
    attn_reduce<<<NS*KVH*QPK, 128>>>(ctx, (float*)d_out);
}

// round 2
// speedup vs baseline: 1.2147x; 1.2147x over previous
#include <cuda_runtime.h>
#include <float.h>

// Problem constants (from reference)
#define NS   32
#define NH   32
#define KVH  8
#define QPK  4
#define HS   128
#define BS   16
#define MB   128
#define PART 256
#define NPARTS 8                 // MB*BS / PART = 2048/256
#define SCALE 0.08838834764831843f   // 1/sqrt(128)

#define QPAD 4                   // smem padding to break qi bank aliasing

// Split-K partial scratch (4MB + 32KB)
__device__ float g_pout[(size_t)NS*KVH*QPK*NPARTS*HS];
__device__ float g_pm[NS*KVH*QPK*NPARTS];
__device__ float g_pl[NS*KVH*QPK*NPARTS];

// One CTA = (kv_head h, partition p, seq n). 256 threads.
// Phase 1: lane = 4*token + qhead; each lane computes a full 128-dim dot
//          (no shuffles). K loads broadcast 4-ways across q-heads.
// Phase 2: two CTA halves over interleaved blocks; each thread owns one d
//          and all 4 heads -> V read exactly once.
__global__ __launch_bounds__(256) void attn_partial(
    const float* __restrict__ q,    const float* __restrict__ knew,
    const float* __restrict__ vnew, const float* __restrict__ kc,
    const float* __restrict__ vc,   const int*   __restrict__ bt,
    const int*   __restrict__ ctx)
{
    int h = blockIdx.x, p = blockIdx.y, n = blockIdx.z;
    int L = ctx[n];
    int start = p * PART;
    if (start >= L) return;               // uniform across CTA
    int ntok = min(PART, L - start);

    __shared__ float s_q[QPK][HS + QPAD];
    __shared__ float s_logits[QPK][PART]; // raw logits, then exp values
    __shared__ float s_m[QPK][8];
    __shared__ float s_mf[QPK];
    __shared__ float s_lred[QPK][8];
    __shared__ float s_acc[QPK][HS];

    int tid  = threadIdx.x;
    int lane = tid & 31, w = tid >> 5;

    // Stage Q for this head-group into smem (padded rows)
    for (int i = tid; i < QPK * HS; i += 256) {
        int qi = i >> 7, dd = i & (HS - 1);
        s_q[qi][dd] = q[((size_t)n*NH + h*QPK + qi)*HS + dd];
    }
    __syncthreads();

    // ---- Phase 1: logits, shuffle-free ----
    int tl_ = lane >> 2;          // token within this warp's group of 8
    int qi  = lane & 3;           // query head within group
    const float4* q4 = (const float4*)s_q[qi];

    for (int pass = 0; pass < PART / 64; pass++) {
        int t = start + pass*64 + w*8 + tl_;
        if (t < L && t - start < PART) {
            float dot = 0.f;
            if (t == L - 1) {
                // new token's K comes from the `key` input (cache not written)
                const float4* kp = (const float4*)(knew + ((size_t)n*KVH + h)*HS);
#pragma unroll 8
                for (int c = 0; c < 32; c++) {
                    float4 kv = kp[c];
                    float4 qv = q4[c];
                    dot += kv.x*qv.x + kv.y*qv.y + kv.z*qv.z + kv.w*qv.w;
                }
            } else {
                int blk = bt[n*MB + (t >> 4)];
                int s   = t & 15;
                // key_cache[b,h,d,s,x]: chunk c -> head dims 4c..4c+3
                const float* base = kc + ((size_t)blk*KVH + h)*(HS*BS) + s*8;
#pragma unroll 8
                for (int c = 0; c < 32; c++) {
                    float4 kv = *(const float4*)(base + (c >> 1)*128 + (c & 1)*4);
                    float4 qv = q4[c];
                    dot += kv.x*qv.x + kv.y*qv.y + kv.z*qv.z + kv.w*qv.w;
                }
            }
            s_logits[qi][t - start] = dot * SCALE;
        }
    }
    __syncthreads();

    // ---- max + exp + sum over the partition (token = tid) ----
    float lg[QPK], mloc[QPK];
#pragma unroll
    for (int k = 0; k < QPK; k++) {
        lg[k]   = (tid < ntok) ? s_logits[k][tid] : -FLT_MAX;
        mloc[k] = lg[k];
    }
#pragma unroll
    for (int off = 16; off; off >>= 1)
#pragma unroll
        for (int k = 0; k < QPK; k++)
            mloc[k] = fmaxf(mloc[k], __shfl_xor_sync(0xffffffffu, mloc[k], off));
    if (lane == 0)
#pragma unroll
        for (int k = 0; k < QPK; k++) s_m[k][w] = mloc[k];
    __syncthreads();
    if (tid < QPK) {
        float m = s_m[tid][0];
#pragma unroll
        for (int i = 1; i < 8; i++) m = fmaxf(m, s_m[tid][i]);
        s_mf[tid] = m;
    }
    __syncthreads();

    float lsum[QPK];
#pragma unroll
    for (int k = 0; k < QPK; k++) {
        float e = (tid < ntok) ? __expf(lg[k] - s_mf[k]) : 0.f;
        s_logits[k][tid] = e;
        lsum[k] = e;
    }
#pragma unroll
    for (int off = 16; off; off >>= 1)
#pragma unroll
        for (int k = 0; k < QPK; k++)
            lsum[k] += __shfl_xor_sync(0xffffffffu, lsum[k], off);
    if (lane == 0)
#pragma unroll
        for (int k = 0; k < QPK; k++) s_lred[k][w] = lsum[k];
    __syncthreads();

    if (tid < QPK) {
        float l = 0.f;
#pragma unroll
        for (int i = 0; i < 8; i++) l += s_lred[tid][i];
        int pid = ((n*KVH + h)*QPK + tid)*NPARTS + p;
        g_pm[pid] = s_mf[tid];
        g_pl[pid] = l;
    }

    // ---- Phase 2: V accumulation, each V element read once ----
    int d  = tid & (HS - 1);
    int hf = tid >> 7;                  // half: 0 or 1
    float acc[QPK] = {0.f, 0.f, 0.f, 0.f};
    int nblk = (ntok + 15) >> 4;
    for (int b = hf; b < nblk; b += 2) {
        int blk = bt[n*MB + (start >> 4) + b];
        // value_cache[b,h,d,s]: fixed d -> 16 contiguous floats over s
        const float* vb = vc + (((size_t)blk*KVH + h)*HS + d)*BS;
#pragma unroll
        for (int ss = 0; ss < 16; ss += 4) {
            float4 v4 = *(const float4*)(vb + ss);
#pragma unroll
            for (int k = 0; k < QPK; k++) {
                float4 wv = *(const float4*)&s_logits[k][b*16 + ss];
                acc[k] += wv.x*v4.x + wv.y*v4.y + wv.z*v4.z + wv.w*v4.w;
            }
        }
    }

    // Correct the new token: replace stale cached V with v_new contribution.
    int tl = L - 1;
    if (tl >= start && tl < start + ntok) {
        int btl = (tl - start) >> 4;
        if ((btl & 1) == hf) {
            int blk = bt[n*MB + (tl >> 4)];
            int s   = tl & 15;
            float vst  = vc[(((size_t)blk*KVH + h)*HS + d)*BS + s];
            float vnw  = vnew[((size_t)n*KVH + h)*HS + d];
            float diff = vnw - vst;
#pragma unroll
            for (int k = 0; k < QPK; k++)
                acc[k] += s_logits[k][tl - start] * diff;
        }
    }

    // Combine the two halves through smem, then write partials.
    if (hf == 0) {
#pragma unroll
        for (int k = 0; k < QPK; k++) s_acc[k][d] = acc[k];
    }
    __syncthreads();
    if (hf == 1) {
#pragma unroll
        for (int k = 0; k < QPK; k++) {
            size_t pid = (size_t)((n*KVH + h)*QPK + k)*NPARTS + p;
            g_pout[pid*HS + d] = s_acc[k][d] + acc[k];
        }
    }
}

// One CTA per (n, h, qi): combine up to NPARTS partials, normalize, write out.
__global__ __launch_bounds__(128) void attn_reduce(
    const int* __restrict__ ctx, float* __restrict__ out)
{
    int g = blockIdx.x;                 // (n*KVH + h)*QPK + qi
    int n = g / (KVH*QPK);
    int head = g % (KVH*QPK);           // h*QPK + qi
    int L = ctx[n];
    int np = (L + PART - 1) / PART;
    int d = threadIdx.x;

    float pm[NPARTS], pl[NPARTS], ov[NPARTS];
#pragma unroll
    for (int p = 0; p < NPARTS; p++) {
        bool ok = p < np;
        pm[p] = ok ? g_pm[g*NPARTS + p] : -FLT_MAX;
        pl[p] = ok ? g_pl[g*NPARTS + p] : 0.f;
        ov[p] = ok ? g_pout[((size_t)g*NPARTS + p)*HS + d] : 0.f;
    }
    float m = pm[0];
#pragma unroll
    for (int p = 1; p < NPARTS; p++) m = fmaxf(m, pm[p]);
    float l = 0.f, o = 0.f;
#pragma unroll
    for (int p = 0; p < NPARTS; p++) {
        float a = __expf(pm[p] - m);
        l += a * pl[p];
        o += a * ov[p];
    }
    out[((size_t)n*NH + head)*HS + d] = o / l;
}

extern "C" void kernel_launch(void* const* d_in, const int* in_sizes, int n_in,
                              void* d_out, int out_size)
{
    const float* q   = (const float*)d_in[0];
    const float* k   = (const float*)d_in[1];
    const float* v   = (const float*)d_in[2];
    const float* kc  = (const float*)d_in[3];
    const float* vc  = (const float*)d_in[4];
    const int*   bt  = (const int*)d_in[5];
    const int*   ctx = (const int*)d_in[6];
    // d_in[7] = slot_mapping (derivable; unused)

    dim3 g1(KVH, NPARTS, NS);
    attn_partial<<<g1, 256>>>(q, k, v, kc, vc, bt, ctx);
    attn_reduce<<<NS*KVH*QPK, 128>>>(ctx, (float*)d_out);
}